// round 1
// baseline (speedup 1.0000x reference)
#include <cuda_runtime.h>
#include <cstdio>

// Problem constants
#define BATCH 2
#define SEQ   2048
#define EMB   1024
#define NHEAD 16
#define HS    64

// Scratch (static device globals — no allocation)
__device__ float g_q [BATCH * SEQ * EMB];   // q_raw [B,T,C]
__device__ float g_kv[BATCH * SEQ * 128];   // [B*T, 128] : cols 0..63 = k, 64..127 = v
__device__ float g_y [BATCH * SEQ * EMB];   // attention output [B,T,C]
__device__ float g_kvw[128 * EMB];          // [Wk ; Wv] rows

// ---------------------------------------------------------------------------
// Concat Wk/Wv into one [128,1024] weight so k and v come from ONE gemm.
// ---------------------------------------------------------------------------
__global__ void concat_w(const float* __restrict__ Wk, const float* __restrict__ Wv)
{
    int i = blockIdx.x * blockDim.x + threadIdx.x;      // 0 .. 131071
    int j = i >> 10;
    int c = i & 1023;
    g_kvw[i] = (j < 64) ? Wk[j * EMB + c] : Wv[(j - 64) * EMB + c];
}

// ---------------------------------------------------------------------------
// SGEMM: C[m][n] = sum_k A[m][k] * B[n][k] (+ bias[n])
// 128x128 block, 256 threads, 8x8 microtile, BK=8, padded smem (no conflicts).
// Dims must be multiples of the tile (they are: M=4096, N in {128,1024}, K=1024).
// ---------------------------------------------------------------------------
__global__ __launch_bounds__(256)
void sgemm_nt(const float* __restrict__ A, const float* __restrict__ B,
              const float* __restrict__ bias, float* __restrict__ C,
              int M, int N, int K)
{
    __shared__ float As[8][132];
    __shared__ float Bs[8][132];

    const int tid = threadIdx.x;
    const int m0 = blockIdx.y * 128;
    const int n0 = blockIdx.x * 128;
    const int ty = tid >> 4;        // 0..15
    const int tx = tid & 15;        // 0..15

    const int lr = tid >> 1;        // 0..127 (row within tile)
    const int lc = (tid & 1) * 4;   // 0 or 4 (k offset)

    const float* Aptr = A + (size_t)(m0 + lr) * K + lc;
    const float* Bptr = B + (size_t)(n0 + lr) * K + lc;

    float acc[8][8];
#pragma unroll
    for (int i = 0; i < 8; i++)
#pragma unroll
        for (int j = 0; j < 8; j++) acc[i][j] = 0.f;

    for (int k0 = 0; k0 < K; k0 += 8) {
        float4 av = *(const float4*)(Aptr + k0);
        float4 bv = *(const float4*)(Bptr + k0);
        As[lc + 0][lr] = av.x;  As[lc + 1][lr] = av.y;
        As[lc + 2][lr] = av.z;  As[lc + 3][lr] = av.w;
        Bs[lc + 0][lr] = bv.x;  Bs[lc + 1][lr] = bv.y;
        Bs[lc + 2][lr] = bv.z;  Bs[lc + 3][lr] = bv.w;
        __syncthreads();

#pragma unroll
        for (int kk = 0; kk < 8; kk++) {
            float4 a0 = *(const float4*)&As[kk][ty * 8];
            float4 a1 = *(const float4*)&As[kk][ty * 8 + 4];
            float4 b0 = *(const float4*)&Bs[kk][tx * 8];
            float4 b1 = *(const float4*)&Bs[kk][tx * 8 + 4];
            float ra[8] = {a0.x, a0.y, a0.z, a0.w, a1.x, a1.y, a1.z, a1.w};
            float rb[8] = {b0.x, b0.y, b0.z, b0.w, b1.x, b1.y, b1.z, b1.w};
#pragma unroll
            for (int i = 0; i < 8; i++)
#pragma unroll
                for (int j = 0; j < 8; j++)
                    acc[i][j] += ra[i] * rb[j];
        }
        __syncthreads();
    }

    float bb[8];
#pragma unroll
    for (int j = 0; j < 8; j++) bb[j] = bias ? bias[n0 + tx * 8 + j] : 0.f;

#pragma unroll
    for (int i = 0; i < 8; i++) {
        float* crow = C + (size_t)(m0 + ty * 8 + i) * N + n0 + tx * 8;
        float4 r0 = make_float4(acc[i][0] + bb[0], acc[i][1] + bb[1],
                                acc[i][2] + bb[2], acc[i][3] + bb[3]);
        float4 r1 = make_float4(acc[i][4] + bb[4], acc[i][5] + bb[5],
                                acc[i][6] + bb[6], acc[i][7] + bb[7]);
        ((float4*)crow)[0] = r0;
        ((float4*)crow)[1] = r1;
    }
}

// ---------------------------------------------------------------------------
// Causal MQA flash attention.
//   grid = (T/128, H, B), block = 128 threads. Thread i owns query row
//   t = qt*128+i for head h. Softmax is fully thread-local (one row / thread).
//   Torch-faithful q scramble: q[b,h,t,d] = q_raw[b, h*128 + t/16, (t%16)*64+d]
// ---------------------------------------------------------------------------
__global__ __launch_bounds__(128, 1)
void mqa_attn(const float* __restrict__ q, const float* __restrict__ kv,
              float* __restrict__ y)
{
    const int qt = (int)gridDim.x - 1 - (int)blockIdx.x;  // big tiles first
    const int h  = blockIdx.y;
    const int b  = blockIdx.z;
    const int i  = threadIdx.x;
    const int t  = qt * 128 + i;

    __shared__ float4 kvs[64][32];   // 64 kv rows x 128 floats (K | V)

    // Q row, pre-scaled by hs^-1/2 = 0.125 (contiguous thanks to the reshape trick)
    float4 qv[16];
    {
        const float4* qp = (const float4*)(q + (size_t)b * SEQ * EMB
                                             + (size_t)(h * 128 + qt * 8 + (i >> 4)) * EMB
                                             + (i & 15) * HS);
#pragma unroll
        for (int d = 0; d < 16; d++) {
            float4 v = qp[d];
            v.x *= 0.125f; v.y *= 0.125f; v.z *= 0.125f; v.w *= 0.125f;
            qv[d] = v;
        }
    }

    float4 o[16];
#pragma unroll
    for (int d = 0; d < 16; d++) o[d] = make_float4(0.f, 0.f, 0.f, 0.f);
    float m = -1e30f, l = 0.f;

    const float4* kv4 = (const float4*)kv;
    const int ntiles = 2 * qt + 2;

    for (int s = 0; s < ntiles; s++) {
        __syncthreads();
        {
            size_t base = ((size_t)b * SEQ + (size_t)s * 64) * 32;
#pragma unroll
            for (int u = 0; u < 16; u++) {
                int idx = i + u * 128;
                ((float4*)kvs)[idx] = kv4[base + idx];
            }
        }
        __syncthreads();

        const int jmax = t - s * 64;   // j valid iff j <= jmax

#pragma unroll 1
        for (int chunk = 0; chunk < 4; chunk++) {
            const int j0 = chunk * 16;
            float sc[16];
            float mt = m;
#pragma unroll
            for (int jj = 0; jj < 16; jj++) {
                const int j = j0 + jj;
                float a0 = 0.f, a1 = 0.f;
#pragma unroll
                for (int d = 0; d < 16; d += 2) {
                    float4 k4 = kvs[j][d];
                    float4 k5 = kvs[j][d + 1];
                    a0 += qv[d].x * k4.x + qv[d].y * k4.y
                        + qv[d].z * k4.z + qv[d].w * k4.w;
                    a1 += qv[d + 1].x * k5.x + qv[d + 1].y * k5.y
                        + qv[d + 1].z * k5.z + qv[d + 1].w * k5.w;
                }
                float acc = (j <= jmax) ? (a0 + a1) : -1e30f;
                sc[jj] = acc;
                mt = fmaxf(mt, acc);
            }
            if (mt > m) {
                float corr = __expf(m - mt);
                l *= corr;
#pragma unroll
                for (int d = 0; d < 16; d++) {
                    o[d].x *= corr; o[d].y *= corr;
                    o[d].z *= corr; o[d].w *= corr;
                }
                m = mt;
            }
#pragma unroll
            for (int jj = 0; jj < 16; jj++) {
                const int j = j0 + jj;
                float p = __expf(sc[jj] - m);
                l += p;
#pragma unroll
                for (int d = 0; d < 16; d++) {
                    float4 v4 = kvs[j][16 + d];
                    o[d].x += p * v4.x; o[d].y += p * v4.y;
                    o[d].z += p * v4.z; o[d].w += p * v4.w;
                }
            }
        }
    }

    const float inv = 1.f / l;
    float4* yp = (float4*)(y + ((size_t)b * SEQ + t) * EMB + h * HS);
#pragma unroll
    for (int d = 0; d < 16; d++)
        yp[d] = make_float4(o[d].x * inv, o[d].y * inv, o[d].z * inv, o[d].w * inv);
}

// ---------------------------------------------------------------------------
extern "C" void kernel_launch(void* const* d_in, const int* in_sizes, int n_in,
                              void* d_out, int out_size)
{
    const float* x  = (const float*)d_in[0];
    const float* Wk = (const float*)d_in[1];
    const float* Wv = (const float*)d_in[2];
    const float* Wq = (const float*)d_in[3];
    const float* Wp = (const float*)d_in[4];
    const float* bp = (const float*)d_in[5];
    float* out = (float*)d_out;

    float *qb, *kvb, *yb, *kvw;
    cudaGetSymbolAddress((void**)&qb,  g_q);
    cudaGetSymbolAddress((void**)&kvb, g_kv);
    cudaGetSymbolAddress((void**)&yb,  g_y);
    cudaGetSymbolAddress((void**)&kvw, g_kvw);

    const int M = BATCH * SEQ;   // 4096

    concat_w<<<512, 256>>>(Wk, Wv);

    // kv = x @ [Wk;Wv]^T   -> [4096, 128]
    sgemm_nt<<<dim3(1, M / 128), 256>>>(x, kvw, nullptr, kvb, M, 128, EMB);

    // q = x @ Wq^T         -> [4096, 1024]
    sgemm_nt<<<dim3(EMB / 128, M / 128), 256>>>(x, Wq, nullptr, qb, M, EMB, EMB);

    // causal MQA flash attention -> y [B,T,C]
    mqa_attn<<<dim3(SEQ / 128, NHEAD, BATCH), 128>>>(qb, kvb, yb);

    // out = y @ Wp^T + bp
    sgemm_nt<<<dim3(EMB / 128, M / 128), 256>>>(yb, Wp, bp, out, M, EMB, EMB);
}

// round 3
// speedup vs baseline: 1.2009x; 1.2009x over previous
#include <cuda_runtime.h>
#include <cuda_bf16.h>
#include <cstdint>

// Problem constants
#define BATCH 2
#define SEQ   2048
#define EMB   1024
#define NHEAD 16
#define HS    64
#define MROWS (BATCH * SEQ)          // 4096

// ---------------------------------------------------------------------------
// Scratch (static device globals — no allocation)
// ---------------------------------------------------------------------------
__device__ float g_q  [MROWS * EMB];     // q_raw [B,T,C] fp32
__device__ float g_kv [MROWS * 128];     // [B*T,128]: 0..63 = k, 64..127 = v
__device__ float g_y  [MROWS * EMB];     // attention output fp32
__device__ float g_kvw[128 * EMB];       // concat [Wk;Wv] fp32

__device__ __nv_bfloat16 g_xhi [MROWS * EMB];
__device__ __nv_bfloat16 g_xlo [MROWS * EMB];
__device__ __nv_bfloat16 g_yhi [MROWS * EMB];
__device__ __nv_bfloat16 g_ylo [MROWS * EMB];
__device__ __nv_bfloat16 g_wqhi[EMB * EMB];
__device__ __nv_bfloat16 g_wqlo[EMB * EMB];
__device__ __nv_bfloat16 g_wphi[EMB * EMB];
__device__ __nv_bfloat16 g_wplo[EMB * EMB];
__device__ __nv_bfloat16 g_kvwhi[128 * EMB];
__device__ __nv_bfloat16 g_kvwlo[128 * EMB];

// ---------------------------------------------------------------------------
// Target-agnostic tensor-core primitives (valid on base sm_103 PTX target)
// ---------------------------------------------------------------------------
__device__ __forceinline__ uint32_t smem_u32(const void* p) {
    uint32_t a;
    asm("{ .reg .u64 t; cvta.to.shared.u64 t, %1; cvt.u32.u64 %0, t; }" : "=r"(a) : "l"(p));
    return a;
}

__device__ __forceinline__ void ldsm_x4(uint32_t& r0, uint32_t& r1,
                                        uint32_t& r2, uint32_t& r3, uint32_t addr)
{
    asm volatile("ldmatrix.sync.aligned.m8n8.x4.shared.b16 {%0,%1,%2,%3}, [%4];"
                 : "=r"(r0), "=r"(r1), "=r"(r2), "=r"(r3) : "r"(addr));
}

__device__ __forceinline__ void mma16816(float* d, const uint32_t* a, const uint32_t* b)
{
    asm volatile("mma.sync.aligned.m16n8k16.row.col.f32.bf16.bf16.f32 "
                 "{%0,%1,%2,%3}, {%4,%5,%6,%7}, {%8,%9}, {%0,%1,%2,%3};"
                 : "+f"(d[0]), "+f"(d[1]), "+f"(d[2]), "+f"(d[3])
                 : "r"(a[0]), "r"(a[1]), "r"(a[2]), "r"(a[3]), "r"(b[0]), "r"(b[1]));
}

// ---------------------------------------------------------------------------
// Elementwise helpers
// ---------------------------------------------------------------------------
__global__ void concat_w(const float* __restrict__ Wk, const float* __restrict__ Wv)
{
    int i = blockIdx.x * blockDim.x + threadIdx.x;
    int j = i >> 10, c = i & 1023;
    g_kvw[i] = (j < 64) ? Wk[j * EMB + c] : Wv[(j - 64) * EMB + c];
}

__global__ void split_hilo(const float* __restrict__ src,
                           __nv_bfloat16* __restrict__ hi,
                           __nv_bfloat16* __restrict__ lo, int n4)
{
    int i = blockIdx.x * blockDim.x + threadIdx.x;
    if (i >= n4) return;
    float4 v = ((const float4*)src)[i];
    __nv_bfloat16 h0 = __float2bfloat16(v.x), h1 = __float2bfloat16(v.y);
    __nv_bfloat16 h2 = __float2bfloat16(v.z), h3 = __float2bfloat16(v.w);
    __nv_bfloat16 l0 = __float2bfloat16(v.x - __bfloat162float(h0));
    __nv_bfloat16 l1 = __float2bfloat16(v.y - __bfloat162float(h1));
    __nv_bfloat16 l2 = __float2bfloat16(v.z - __bfloat162float(h2));
    __nv_bfloat16 l3 = __float2bfloat16(v.w - __bfloat162float(h3));
    ((__nv_bfloat162*)hi)[2 * i]     = __nv_bfloat162(h0, h1);
    ((__nv_bfloat162*)hi)[2 * i + 1] = __nv_bfloat162(h2, h3);
    ((__nv_bfloat162*)lo)[2 * i]     = __nv_bfloat162(l0, l1);
    ((__nv_bfloat162*)lo)[2 * i + 1] = __nv_bfloat162(l2, l3);
}

// ---------------------------------------------------------------------------
// bf16 3-split GEMM on mma.sync:  C = sum_{ph} Aph @ Bph^T  (+bias)
//   A*, B* row-major with 1024-element rows. Tile 128x128, BK=32, 256 thr.
//   smem rows are 80B (32 bf16 + 8 pad): ldmatrix bank-quads r*5 mod 8 = bijection.
// ---------------------------------------------------------------------------
#define NITER 96   // 3 phases x 32 chunks of K=32

__global__ __launch_bounds__(256, 1)
void gemm3_mma(const __nv_bfloat16* __restrict__ A0, const __nv_bfloat16* __restrict__ A1,
               const __nv_bfloat16* __restrict__ A2,
               const __nv_bfloat16* __restrict__ B0, const __nv_bfloat16* __restrict__ B1,
               const __nv_bfloat16* __restrict__ B2,
               const float* __restrict__ bias, float* __restrict__ C, int ldc)
{
    __shared__ __align__(16) char sm[2][20480];   // per buf: A @0 (10240B), B @10240

    const int tid  = threadIdx.x;
    const int wid  = tid >> 5;
    const int lane = tid & 31;
    const int m0 = blockIdx.y * 128;
    const int n0 = blockIdx.x * 128;
    const int wm = (wid & 1) << 6;      // warp m offset (0/64)
    const int wn = (wid >> 1) << 5;     // warp n offset (0..96)

    // loader mapping: thread -> (row, 32B segment)
    const int lrow = tid >> 1;
    const int lcb  = (tid & 1) * 32;

    // ldmatrix per-lane source rows
    const int lt = lane >> 3;   // tile group 0..3
    const int lr = lane & 7;
    // A tiles: t0:(m+0..7,k0-7) t1:(m+8..15,k0-7) t2:(m+0..7,k8-15) t3:(m+8..15,k8-15)
    const uint32_t a_off = (uint32_t)(wm + lr + ((lt & 1) << 3)) * 80 + ((lt >> 1) << 4);
    // B tiles: t0:(n+0..7,k0-7) t1:(n+0..7,k8-15) t2:(n+8..15,k0-7) t3:(n+8..15,k8-15)
    const uint32_t b_off = 10240u + (uint32_t)(wn + lr + ((lt >> 1) << 3)) * 80 + ((lt & 1) << 4);

    const uint32_t sbase = smem_u32(sm);
    const uint32_t sts_a = (uint32_t)lrow * 80 + lcb;
    const uint32_t sts_b = 10240u + (uint32_t)lrow * 80 + lcb;

    float d[4][4][4];
#pragma unroll
    for (int mi = 0; mi < 4; mi++)
#pragma unroll
        for (int ni = 0; ni < 4; ni++)
#pragma unroll
            for (int q = 0; q < 4; q++) d[mi][ni][q] = 0.f;

    float4 pre[4];
    {
        const char* ab = (const char*)(A0 + (size_t)(m0 + lrow) * EMB);
        const char* bb = (const char*)(B0 + (size_t)(n0 + lrow) * EMB);
        pre[0] = *(const float4*)(ab + lcb);
        pre[1] = *(const float4*)(ab + lcb + 16);
        pre[2] = *(const float4*)(bb + lcb);
        pre[3] = *(const float4*)(bb + lcb + 16);
    }

    for (int c = 0; c < NITER; c++) {
        const int buf = c & 1;
        {
            char* s = (char*)sm + buf * 20480;
            *(float4*)(s + sts_a)      = pre[0];
            *(float4*)(s + sts_a + 16) = pre[1];
            *(float4*)(s + sts_b)      = pre[2];
            *(float4*)(s + sts_b + 16) = pre[3];
        }
        __syncthreads();

        // prefetch next chunk (overlaps ldsm/mma)
        if (c + 1 < NITER) {
            const int cn = c + 1;
            const int ph = cn >> 5;
            const int k0 = (cn & 31) << 5;
            const __nv_bfloat16* Ap = (ph == 0) ? A0 : (ph == 1) ? A1 : A2;
            const __nv_bfloat16* Bp = (ph == 0) ? B0 : (ph == 1) ? B1 : B2;
            const char* ab = (const char*)(Ap + (size_t)(m0 + lrow) * EMB + k0);
            const char* bb = (const char*)(Bp + (size_t)(n0 + lrow) * EMB + k0);
            pre[0] = *(const float4*)(ab + lcb);
            pre[1] = *(const float4*)(ab + lcb + 16);
            pre[2] = *(const float4*)(bb + lcb);
            pre[3] = *(const float4*)(bb + lcb + 16);
        }

        const uint32_t abase = sbase + buf * 20480 + a_off;
        const uint32_t bbase = sbase + buf * 20480 + b_off;
#pragma unroll
        for (int ks = 0; ks < 2; ks++) {
            uint32_t a[4][4], b[2][4];
#pragma unroll
            for (int mi = 0; mi < 4; mi++)
                ldsm_x4(a[mi][0], a[mi][1], a[mi][2], a[mi][3],
                        abase + (uint32_t)mi * (16 * 80) + ks * 32);
#pragma unroll
            for (int nt = 0; nt < 2; nt++)
                ldsm_x4(b[nt][0], b[nt][1], b[nt][2], b[nt][3],
                        bbase + (uint32_t)nt * (16 * 80) + ks * 32);
#pragma unroll
            for (int mi = 0; mi < 4; mi++)
#pragma unroll
                for (int ni = 0; ni < 4; ni++)
                    mma16816(d[mi][ni], a[mi], &b[ni >> 1][(ni & 1) * 2]);
        }
        // single barrier per iteration is sufficient: writes for chunk c+1 go to
        // the other buffer, and writes for c+2 happen only after sync(c+1), by
        // which time every thread has finished mma(c).
    }

    // epilogue
    const int erow = lane >> 2;
    const int ecol = (lane & 3) << 1;
#pragma unroll
    for (int mi = 0; mi < 4; mi++) {
#pragma unroll
        for (int ni = 0; ni < 4; ni++) {
            const int r = m0 + wm + mi * 16 + erow;
            const int cc = n0 + wn + ni * 8 + ecol;
            float bx = 0.f, by = 0.f;
            if (bias) { bx = bias[cc]; by = bias[cc + 1]; }
            float2* p0 = (float2*)(C + (size_t)r * ldc + cc);
            float2* p1 = (float2*)(C + (size_t)(r + 8) * ldc + cc);
            *p0 = make_float2(d[mi][ni][0] + bx, d[mi][ni][1] + by);
            *p1 = make_float2(d[mi][ni][2] + bx, d[mi][ni][3] + by);
        }
    }
}

// ---------------------------------------------------------------------------
// Causal MQA flash attention (unchanged — proven correct, round 1)
// ---------------------------------------------------------------------------
__global__ __launch_bounds__(128, 1)
void mqa_attn(const float* __restrict__ q, const float* __restrict__ kv,
              float* __restrict__ y)
{
    const int qt = (int)gridDim.x - 1 - (int)blockIdx.x;
    const int h  = blockIdx.y;
    const int b  = blockIdx.z;
    const int i  = threadIdx.x;
    const int t  = qt * 128 + i;

    __shared__ float4 kvs[64][32];

    float4 qv[16];
    {
        const float4* qp = (const float4*)(q + (size_t)b * SEQ * EMB
                                             + (size_t)(h * 128 + qt * 8 + (i >> 4)) * EMB
                                             + (i & 15) * HS);
#pragma unroll
        for (int d = 0; d < 16; d++) {
            float4 v = qp[d];
            v.x *= 0.125f; v.y *= 0.125f; v.z *= 0.125f; v.w *= 0.125f;
            qv[d] = v;
        }
    }

    float4 o[16];
#pragma unroll
    for (int d = 0; d < 16; d++) o[d] = make_float4(0.f, 0.f, 0.f, 0.f);
    float m = -1e30f, l = 0.f;

    const float4* kv4 = (const float4*)kv;
    const int ntiles = 2 * qt + 2;

    for (int s = 0; s < ntiles; s++) {
        __syncthreads();
        {
            size_t base = ((size_t)b * SEQ + (size_t)s * 64) * 32;
#pragma unroll
            for (int u = 0; u < 16; u++) {
                int idx = i + u * 128;
                ((float4*)kvs)[idx] = kv4[base + idx];
            }
        }
        __syncthreads();

        const int jmax = t - s * 64;

#pragma unroll 1
        for (int chunk = 0; chunk < 4; chunk++) {
            const int j0 = chunk * 16;
            float sc[16];
            float mt = m;
#pragma unroll
            for (int jj = 0; jj < 16; jj++) {
                const int j = j0 + jj;
                float a0 = 0.f, a1 = 0.f;
#pragma unroll
                for (int d = 0; d < 16; d += 2) {
                    float4 k4 = kvs[j][d];
                    float4 k5 = kvs[j][d + 1];
                    a0 += qv[d].x * k4.x + qv[d].y * k4.y
                        + qv[d].z * k4.z + qv[d].w * k4.w;
                    a1 += qv[d + 1].x * k5.x + qv[d + 1].y * k5.y
                        + qv[d + 1].z * k5.z + qv[d + 1].w * k5.w;
                }
                float acc = (j <= jmax) ? (a0 + a1) : -1e30f;
                sc[jj] = acc;
                mt = fmaxf(mt, acc);
            }
            if (mt > m) {
                float corr = __expf(m - mt);
                l *= corr;
#pragma unroll
                for (int d = 0; d < 16; d++) {
                    o[d].x *= corr; o[d].y *= corr;
                    o[d].z *= corr; o[d].w *= corr;
                }
                m = mt;
            }
#pragma unroll
            for (int jj = 0; jj < 16; jj++) {
                const int j = j0 + jj;
                float p = __expf(sc[jj] - m);
                l += p;
#pragma unroll
                for (int d = 0; d < 16; d++) {
                    float4 v4 = kvs[j][16 + d];
                    o[d].x += p * v4.x; o[d].y += p * v4.y;
                    o[d].z += p * v4.z; o[d].w += p * v4.w;
                }
            }
        }
    }

    const float inv = 1.f / l;
    float4* yp = (float4*)(y + ((size_t)b * SEQ + t) * EMB + h * HS);
#pragma unroll
    for (int d = 0; d < 16; d++)
        yp[d] = make_float4(o[d].x * inv, o[d].y * inv, o[d].z * inv, o[d].w * inv);
}

// ---------------------------------------------------------------------------
extern "C" void kernel_launch(void* const* d_in, const int* in_sizes, int n_in,
                              void* d_out, int out_size)
{
    const float* x  = (const float*)d_in[0];
    const float* Wk = (const float*)d_in[1];
    const float* Wv = (const float*)d_in[2];
    const float* Wq = (const float*)d_in[3];
    const float* Wp = (const float*)d_in[4];
    const float* bp = (const float*)d_in[5];
    float* out = (float*)d_out;

    float *qb, *kvb, *yb, *kvw;
    cudaGetSymbolAddress((void**)&qb,  g_q);
    cudaGetSymbolAddress((void**)&kvb, g_kv);
    cudaGetSymbolAddress((void**)&yb,  g_y);
    cudaGetSymbolAddress((void**)&kvw, g_kvw);
    __nv_bfloat16 *xhi, *xlo, *yhi, *ylo, *wqhi, *wqlo, *wphi, *wplo, *kvwhi, *kvwlo;
    cudaGetSymbolAddress((void**)&xhi, g_xhi);   cudaGetSymbolAddress((void**)&xlo, g_xlo);
    cudaGetSymbolAddress((void**)&yhi, g_yhi);   cudaGetSymbolAddress((void**)&ylo, g_ylo);
    cudaGetSymbolAddress((void**)&wqhi, g_wqhi); cudaGetSymbolAddress((void**)&wqlo, g_wqlo);
    cudaGetSymbolAddress((void**)&wphi, g_wphi); cudaGetSymbolAddress((void**)&wplo, g_wplo);
    cudaGetSymbolAddress((void**)&kvwhi, g_kvwhi); cudaGetSymbolAddress((void**)&kvwlo, g_kvwlo);

    // precision splits
    concat_w<<<512, 256>>>(Wk, Wv);
    split_hilo<<<(MROWS * EMB / 4 + 255) / 256, 256>>>(x,   xhi,  xlo,  MROWS * EMB / 4);
    split_hilo<<<(128 * EMB / 4 + 255) / 256, 256>>>(kvw, kvwhi, kvwlo, 128 * EMB / 4);
    split_hilo<<<(EMB * EMB / 4 + 255) / 256, 256>>>(Wq,  wqhi, wqlo, EMB * EMB / 4);
    split_hilo<<<(EMB * EMB / 4 + 255) / 256, 256>>>(Wp,  wphi, wplo, EMB * EMB / 4);

    // kv = x @ [Wk;Wv]^T  -> [4096,128]
    gemm3_mma<<<dim3(1, MROWS / 128), 256>>>(
        xhi, xhi, xlo, kvwhi, kvwlo, kvwhi, nullptr, kvb, 128);

    // q = x @ Wq^T        -> [4096,1024]
    gemm3_mma<<<dim3(EMB / 128, MROWS / 128), 256>>>(
        xhi, xhi, xlo, wqhi, wqlo, wqhi, nullptr, qb, EMB);

    // attention
    mqa_attn<<<dim3(SEQ / 128, NHEAD, BATCH), 128>>>(qb, kvb, yb);

    // out = y @ Wp^T + bp
    split_hilo<<<(MROWS * EMB / 4 + 255) / 256, 256>>>(yb, yhi, ylo, MROWS * EMB / 4);
    gemm3_mma<<<dim3(EMB / 128, MROWS / 128), 256>>>(
        yhi, yhi, ylo, wphi, wplo, wphi, bp, out, EMB);
}

// round 4
// speedup vs baseline: 1.2454x; 1.0370x over previous
#include <cuda_runtime.h>
#include <cuda_bf16.h>
#include <cstdint>

// Problem constants
#define BATCH 2
#define SEQ   2048
#define EMB   1024
#define NHEAD 16
#define HS    64
#define MROWS (BATCH * SEQ)          // 4096

// ---------------------------------------------------------------------------
// Scratch (static device globals — no allocation)
// ---------------------------------------------------------------------------
__device__ float g_q  [MROWS * EMB];
__device__ float g_kv [MROWS * 128];
__device__ float g_y  [MROWS * EMB];
__device__ float g_kvw[128 * EMB];

__device__ __nv_bfloat16 g_xhi [MROWS * EMB];
__device__ __nv_bfloat16 g_xlo [MROWS * EMB];
__device__ __nv_bfloat16 g_yhi [MROWS * EMB];
__device__ __nv_bfloat16 g_ylo [MROWS * EMB];
__device__ __nv_bfloat16 g_wqhi[EMB * EMB];
__device__ __nv_bfloat16 g_wqlo[EMB * EMB];
__device__ __nv_bfloat16 g_wphi[EMB * EMB];
__device__ __nv_bfloat16 g_wplo[EMB * EMB];
__device__ __nv_bfloat16 g_kvwhi[128 * EMB];
__device__ __nv_bfloat16 g_kvwlo[128 * EMB];

// ---------------------------------------------------------------------------
// Target-agnostic primitives (valid at .target sm_103)
// ---------------------------------------------------------------------------
__device__ __forceinline__ uint32_t smem_u32(const void* p) {
    uint32_t a;
    asm("{ .reg .u64 t; cvta.to.shared.u64 t, %1; cvt.u32.u64 %0, t; }" : "=r"(a) : "l"(p));
    return a;
}
__device__ __forceinline__ void ldsm_x4(uint32_t& r0, uint32_t& r1,
                                        uint32_t& r2, uint32_t& r3, uint32_t addr)
{
    asm volatile("ldmatrix.sync.aligned.m8n8.x4.shared.b16 {%0,%1,%2,%3}, [%4];"
                 : "=r"(r0), "=r"(r1), "=r"(r2), "=r"(r3) : "r"(addr));
}
__device__ __forceinline__ void mma16816(float* d, const uint32_t* a, const uint32_t* b)
{
    asm volatile("mma.sync.aligned.m16n8k16.row.col.f32.bf16.bf16.f32 "
                 "{%0,%1,%2,%3}, {%4,%5,%6,%7}, {%8,%9}, {%0,%1,%2,%3};"
                 : "+f"(d[0]), "+f"(d[1]), "+f"(d[2]), "+f"(d[3])
                 : "r"(a[0]), "r"(a[1]), "r"(a[2]), "r"(a[3]), "r"(b[0]), "r"(b[1]));
}
__device__ __forceinline__ void cp_async16(uint32_t saddr, const void* gptr) {
    asm volatile("cp.async.cg.shared.global [%0], [%1], 16;" :: "r"(saddr), "l"(gptr));
}
#define CP_COMMIT() asm volatile("cp.async.commit_group;" ::: "memory")
#define CP_WAIT2()  asm volatile("cp.async.wait_group 2;" ::: "memory")

// exp2 on the FMA pipe (no MUFU). Valid for y <= ~1; clamps below -100.
__device__ __forceinline__ float exp2_fast(float y) {
    y = fmaxf(y, -100.f);
    float z = y + 12582912.f;                       // round-to-nearest via magic
    int   n = __float_as_int(z) - 0x4B400000;       // integer part of y
    float f = y - (z - 12582912.f);                 // f in [-0.5, 0.5]
    float p =             1.3333558e-3f;
    p = fmaf(p, f, 9.6181291e-3f);
    p = fmaf(p, f, 5.5504109e-2f);
    p = fmaf(p, f, 2.4022651e-1f);
    p = fmaf(p, f, 6.9314718e-1f);
    p = fmaf(p, f, 1.0f);
    return p * __int_as_float((n + 127) << 23);
}

// ---------------------------------------------------------------------------
// Elementwise helpers
// ---------------------------------------------------------------------------
__global__ void concat_w(const float* __restrict__ Wk, const float* __restrict__ Wv)
{
    int i = blockIdx.x * blockDim.x + threadIdx.x;
    int j = i >> 10, c = i & 1023;
    g_kvw[i] = (j < 64) ? Wk[j * EMB + c] : Wv[(j - 64) * EMB + c];
}

__global__ void split_hilo(const float* __restrict__ src,
                           __nv_bfloat16* __restrict__ hi,
                           __nv_bfloat16* __restrict__ lo, int n4)
{
    int i = blockIdx.x * blockDim.x + threadIdx.x;
    if (i >= n4) return;
    float4 v = ((const float4*)src)[i];
    __nv_bfloat16 h0 = __float2bfloat16(v.x), h1 = __float2bfloat16(v.y);
    __nv_bfloat16 h2 = __float2bfloat16(v.z), h3 = __float2bfloat16(v.w);
    __nv_bfloat16 l0 = __float2bfloat16(v.x - __bfloat162float(h0));
    __nv_bfloat16 l1 = __float2bfloat16(v.y - __bfloat162float(h1));
    __nv_bfloat16 l2 = __float2bfloat16(v.z - __bfloat162float(h2));
    __nv_bfloat16 l3 = __float2bfloat16(v.w - __bfloat162float(h3));
    ((__nv_bfloat162*)hi)[2 * i]     = __nv_bfloat162(h0, h1);
    ((__nv_bfloat162*)hi)[2 * i + 1] = __nv_bfloat162(h2, h3);
    ((__nv_bfloat162*)lo)[2 * i]     = __nv_bfloat162(l0, l1);
    ((__nv_bfloat162*)lo)[2 * i + 1] = __nv_bfloat162(l2, l3);
}

// ---------------------------------------------------------------------------
// bf16 3-split GEMM on mma.sync with 4-stage cp.async pipeline.
//   C = A0@B0^T + A1@B1^T + A2@B2^T (+bias). Rows are EMB=1024 elements.
//   Tile 128x128, BK=32, 256 threads. smem rows 80B (64B data + 16B pad):
//   ldmatrix bank-quad = r*5 mod 8 -> conflict-free.
// ---------------------------------------------------------------------------
#define NITER  96           // 3 phases x 32 chunks of K=32
#define STAGEB 20480        // per-stage bytes: A 10240 + B 10240
#define GSMEM  (4 * STAGEB)

__global__ __launch_bounds__(256, 1)
void gemm3_mma(const __nv_bfloat16* __restrict__ A0, const __nv_bfloat16* __restrict__ A1,
               const __nv_bfloat16* __restrict__ A2,
               const __nv_bfloat16* __restrict__ B0, const __nv_bfloat16* __restrict__ B1,
               const __nv_bfloat16* __restrict__ B2,
               const float* __restrict__ bias, float* __restrict__ C, int ldc)
{
    extern __shared__ __align__(16) char sm[];

    const int tid  = threadIdx.x;
    const int wid  = tid >> 5;
    const int lane = tid & 31;
    const int m0 = blockIdx.y * 128;
    const int n0 = blockIdx.x * 128;
    const int wm = (wid & 1) << 6;
    const int wn = (wid >> 1) << 5;

    // ldmatrix per-lane source offsets (same verified mapping as round 3)
    const int lt = lane >> 3;
    const int lr = lane & 7;
    const uint32_t a_off = (uint32_t)(wm + lr + ((lt & 1) << 3)) * 80 + ((lt >> 1) << 4);
    const uint32_t b_off = 10240u + (uint32_t)(wn + lr + ((lt >> 1) << 3)) * 80 + ((lt & 1) << 4);
    const uint32_t sbase = smem_u32(sm);

    // cp.async chunk mapping: 512 16B-chunks each for A and B; 2+2 per thread
    const int r0c = tid >> 2,         s0c = tid & 3;          // chunk tid
    const int r1c = (tid + 256) >> 2, s1c = (tid + 256) & 3;  // chunk tid+256

    float d[4][4][4];
#pragma unroll
    for (int mi = 0; mi < 4; mi++)
#pragma unroll
        for (int ni = 0; ni < 4; ni++)
#pragma unroll
            for (int q = 0; q < 4; q++) d[mi][ni][q] = 0.f;

#define LOAD_STAGE(bufi, ci) do {                                                  \
    const int _ph = (ci) >> 5;                                                     \
    const int _k0 = ((ci) & 31) << 5;                                              \
    const __nv_bfloat16* _Ap = (_ph == 0) ? A0 : (_ph == 1) ? A1 : A2;             \
    const __nv_bfloat16* _Bp = (_ph == 0) ? B0 : (_ph == 1) ? B1 : B2;             \
    const uint32_t _sb = sbase + (uint32_t)(bufi) * STAGEB;                        \
    cp_async16(_sb + (uint32_t)r0c * 80 + s0c * 16,                                \
               _Ap + (size_t)(m0 + r0c) * EMB + _k0 + s0c * 8);                    \
    cp_async16(_sb + (uint32_t)r1c * 80 + s1c * 16,                                \
               _Ap + (size_t)(m0 + r1c) * EMB + _k0 + s1c * 8);                    \
    cp_async16(_sb + 10240u + (uint32_t)r0c * 80 + s0c * 16,                       \
               _Bp + (size_t)(n0 + r0c) * EMB + _k0 + s0c * 8);                    \
    cp_async16(_sb + 10240u + (uint32_t)r1c * 80 + s1c * 16,                       \
               _Bp + (size_t)(n0 + r1c) * EMB + _k0 + s1c * 8);                    \
} while (0)

    // prologue: 3 stages in flight
    LOAD_STAGE(0, 0); CP_COMMIT();
    LOAD_STAGE(1, 1); CP_COMMIT();
    LOAD_STAGE(2, 2); CP_COMMIT();

    for (int c = 0; c < NITER; c++) {
        CP_WAIT2();
        __syncthreads();

        // issue stage c+3 (overwrites buffer (c-1)&3 — safe after the barrier)
        if (c + 3 < NITER) LOAD_STAGE((c + 3) & 3, c + 3);
        CP_COMMIT();

        const uint32_t abase = sbase + (uint32_t)(c & 3) * STAGEB + a_off;
        const uint32_t bbase = sbase + (uint32_t)(c & 3) * STAGEB + b_off;
#pragma unroll
        for (int ks = 0; ks < 2; ks++) {
            uint32_t a[4][4], b[2][4];
#pragma unroll
            for (int mi = 0; mi < 4; mi++)
                ldsm_x4(a[mi][0], a[mi][1], a[mi][2], a[mi][3],
                        abase + (uint32_t)mi * (16 * 80) + ks * 32);
#pragma unroll
            for (int nt = 0; nt < 2; nt++)
                ldsm_x4(b[nt][0], b[nt][1], b[nt][2], b[nt][3],
                        bbase + (uint32_t)nt * (16 * 80) + ks * 32);
#pragma unroll
            for (int mi = 0; mi < 4; mi++)
#pragma unroll
                for (int ni = 0; ni < 4; ni++)
                    mma16816(d[mi][ni], a[mi], &b[ni >> 1][(ni & 1) * 2]);
        }
        __syncthreads();
    }

    // epilogue
    const int erow = lane >> 2;
    const int ecol = (lane & 3) << 1;
#pragma unroll
    for (int mi = 0; mi < 4; mi++) {
#pragma unroll
        for (int ni = 0; ni < 4; ni++) {
            const int r = m0 + wm + mi * 16 + erow;
            const int cc = n0 + wn + ni * 8 + ecol;
            float bx = 0.f, by = 0.f;
            if (bias) { bx = bias[cc]; by = bias[cc + 1]; }
            float2* p0 = (float2*)(C + (size_t)r * ldc + cc);
            float2* p1 = (float2*)(C + (size_t)(r + 8) * ldc + cc);
            *p0 = make_float2(d[mi][ni][0] + bx, d[mi][ni][1] + by);
            *p1 = make_float2(d[mi][ni][2] + bx, d[mi][ni][3] + by);
        }
    }
#undef LOAD_STAGE
}

// ---------------------------------------------------------------------------
// Causal MQA flash attention — scores in log2 domain, exp on the FMA pipe.
// ---------------------------------------------------------------------------
__global__ __launch_bounds__(128, 1)
void mqa_attn(const float* __restrict__ q, const float* __restrict__ kv,
              float* __restrict__ y)
{
    const int qt = (int)gridDim.x - 1 - (int)blockIdx.x;
    const int h  = blockIdx.y;
    const int b  = blockIdx.z;
    const int i  = threadIdx.x;
    const int t  = qt * 128 + i;

    __shared__ float4 kvs[64][32];

    // Q row pre-scaled by hs^-0.5 * log2(e) -> scores in log2 units
    const float qscale = 0.125f * 1.44269504088896340736f;
    float4 qv[16];
    {
        const float4* qp = (const float4*)(q + (size_t)b * SEQ * EMB
                                             + (size_t)(h * 128 + qt * 8 + (i >> 4)) * EMB
                                             + (i & 15) * HS);
#pragma unroll
        for (int d = 0; d < 16; d++) {
            float4 v = qp[d];
            v.x *= qscale; v.y *= qscale; v.z *= qscale; v.w *= qscale;
            qv[d] = v;
        }
    }

    float4 o[16];
#pragma unroll
    for (int d = 0; d < 16; d++) o[d] = make_float4(0.f, 0.f, 0.f, 0.f);
    float m = -1e30f, l = 0.f;

    const float4* kv4 = (const float4*)kv;
    const int ntiles = 2 * qt + 2;

    for (int s = 0; s < ntiles; s++) {
        __syncthreads();
        {
            size_t base = ((size_t)b * SEQ + (size_t)s * 64) * 32;
#pragma unroll
            for (int u = 0; u < 16; u++) {
                int idx = i + u * 128;
                ((float4*)kvs)[idx] = kv4[base + idx];
            }
        }
        __syncthreads();

        const int jmax = t - s * 64;

#pragma unroll 1
        for (int chunk = 0; chunk < 4; chunk++) {
            const int j0 = chunk * 16;
            float sc[16];
            float mt = m;
#pragma unroll
            for (int jj = 0; jj < 16; jj++) {
                const int j = j0 + jj;
                float a0 = 0.f, a1 = 0.f;
#pragma unroll
                for (int d = 0; d < 16; d += 2) {
                    float4 k4 = kvs[j][d];
                    float4 k5 = kvs[j][d + 1];
                    a0 += qv[d].x * k4.x + qv[d].y * k4.y
                        + qv[d].z * k4.z + qv[d].w * k4.w;
                    a1 += qv[d + 1].x * k5.x + qv[d + 1].y * k5.y
                        + qv[d + 1].z * k5.z + qv[d + 1].w * k5.w;
                }
                float acc = (j <= jmax) ? (a0 + a1) : -1e30f;
                sc[jj] = acc;
                mt = fmaxf(mt, acc);
            }
            if (mt > m) {
                float corr = exp2_fast(m - mt);
                l *= corr;
#pragma unroll
                for (int d = 0; d < 16; d++) {
                    o[d].x *= corr; o[d].y *= corr;
                    o[d].z *= corr; o[d].w *= corr;
                }
                m = mt;
            }
#pragma unroll
            for (int jj = 0; jj < 16; jj++) {
                const int j = j0 + jj;
                float p = exp2_fast(sc[jj] - m);
                l += p;
#pragma unroll
                for (int d = 0; d < 16; d++) {
                    float4 v4 = kvs[j][16 + d];
                    o[d].x += p * v4.x; o[d].y += p * v4.y;
                    o[d].z += p * v4.z; o[d].w += p * v4.w;
                }
            }
        }
    }

    const float inv = 1.f / l;
    float4* yp = (float4*)(y + ((size_t)b * SEQ + t) * EMB + h * HS);
#pragma unroll
    for (int d = 0; d < 16; d++)
        yp[d] = make_float4(o[d].x * inv, o[d].y * inv, o[d].z * inv, o[d].w * inv);
}

// ---------------------------------------------------------------------------
extern "C" void kernel_launch(void* const* d_in, const int* in_sizes, int n_in,
                              void* d_out, int out_size)
{
    const float* x  = (const float*)d_in[0];
    const float* Wk = (const float*)d_in[1];
    const float* Wv = (const float*)d_in[2];
    const float* Wq = (const float*)d_in[3];
    const float* Wp = (const float*)d_in[4];
    const float* bp = (const float*)d_in[5];
    float* out = (float*)d_out;

    float *qb, *kvb, *yb, *kvw;
    cudaGetSymbolAddress((void**)&qb,  g_q);
    cudaGetSymbolAddress((void**)&kvb, g_kv);
    cudaGetSymbolAddress((void**)&yb,  g_y);
    cudaGetSymbolAddress((void**)&kvw, g_kvw);
    __nv_bfloat16 *xhi, *xlo, *yhi, *ylo, *wqhi, *wqlo, *wphi, *wplo, *kvwhi, *kvwlo;
    cudaGetSymbolAddress((void**)&xhi, g_xhi);   cudaGetSymbolAddress((void**)&xlo, g_xlo);
    cudaGetSymbolAddress((void**)&yhi, g_yhi);   cudaGetSymbolAddress((void**)&ylo, g_ylo);
    cudaGetSymbolAddress((void**)&wqhi, g_wqhi); cudaGetSymbolAddress((void**)&wqlo, g_wqlo);
    cudaGetSymbolAddress((void**)&wphi, g_wphi); cudaGetSymbolAddress((void**)&wplo, g_wplo);
    cudaGetSymbolAddress((void**)&kvwhi, g_kvwhi); cudaGetSymbolAddress((void**)&kvwlo, g_kvwlo);

    cudaFuncSetAttribute(gemm3_mma, cudaFuncAttributeMaxDynamicSharedMemorySize, GSMEM);

    // precision splits
    concat_w<<<512, 256>>>(Wk, Wv);
    split_hilo<<<(MROWS * EMB / 4 + 255) / 256, 256>>>(x,   xhi,  xlo,  MROWS * EMB / 4);
    split_hilo<<<(128 * EMB / 4 + 255) / 256, 256>>>(kvw, kvwhi, kvwlo, 128 * EMB / 4);
    split_hilo<<<(EMB * EMB / 4 + 255) / 256, 256>>>(Wq,  wqhi, wqlo, EMB * EMB / 4);
    split_hilo<<<(EMB * EMB / 4 + 255) / 256, 256>>>(Wp,  wphi, wplo, EMB * EMB / 4);

    // kv = x @ [Wk;Wv]^T  -> [4096,128]
    gemm3_mma<<<dim3(1, MROWS / 128), 256, GSMEM>>>(
        xhi, xhi, xlo, kvwhi, kvwlo, kvwhi, nullptr, kvb, 128);

    // q = x @ Wq^T        -> [4096,1024]
    gemm3_mma<<<dim3(EMB / 128, MROWS / 128), 256, GSMEM>>>(
        xhi, xhi, xlo, wqhi, wqlo, wqhi, nullptr, qb, EMB);

    // attention
    mqa_attn<<<dim3(SEQ / 128, NHEAD, BATCH), 128>>>(qb, kvb, yb);

    // out = y @ Wp^T + bp
    split_hilo<<<(MROWS * EMB / 4 + 255) / 256, 256>>>(yb, yhi, ylo, MROWS * EMB / 4);
    gemm3_mma<<<dim3(EMB / 128, MROWS / 128), 256, GSMEM>>>(
        yhi, yhi, ylo, wphi, wplo, wphi, bp, out, EMB);
}

// round 6
// speedup vs baseline: 2.7883x; 2.2389x over previous
#include <cuda_runtime.h>
#include <cuda_bf16.h>
#include <cstdint>

// Problem constants
#define BATCH 2
#define SEQ   2048
#define EMB   1024
#define NHEAD 16
#define HS    64
#define MROWS (BATCH * SEQ)          // 4096

// ---------------------------------------------------------------------------
// Scratch (static device globals — no allocation)
// ---------------------------------------------------------------------------
__device__ float g_q  [MROWS * EMB];
__device__ float g_kv [MROWS * 128];
__device__ float g_y  [MROWS * EMB];
__device__ float g_kvw[128 * EMB];

__device__ __nv_bfloat16 g_xhi [MROWS * EMB];   // also reused as q_hi after q-gemm
__device__ __nv_bfloat16 g_xlo [MROWS * EMB];   // also reused as q_lo
__device__ __nv_bfloat16 g_yhi [MROWS * EMB];
__device__ __nv_bfloat16 g_ylo [MROWS * EMB];
__device__ __nv_bfloat16 g_wqhi[EMB * EMB];
__device__ __nv_bfloat16 g_wqlo[EMB * EMB];
__device__ __nv_bfloat16 g_wphi[EMB * EMB];
__device__ __nv_bfloat16 g_wplo[EMB * EMB];
__device__ __nv_bfloat16 g_kvwhi[128 * EMB];
__device__ __nv_bfloat16 g_kvwlo[128 * EMB];
__device__ __nv_bfloat16 g_kvhi[MROWS * 128];
__device__ __nv_bfloat16 g_kvlo[MROWS * 128];

// ---------------------------------------------------------------------------
// Target-agnostic primitives (valid at .target sm_103)
// ---------------------------------------------------------------------------
__device__ __forceinline__ uint32_t smem_u32(const void* p) {
    uint32_t a;
    asm("{ .reg .u64 t; cvta.to.shared.u64 t, %1; cvt.u32.u64 %0, t; }" : "=r"(a) : "l"(p));
    return a;
}
__device__ __forceinline__ void ldsm_x4(uint32_t& r0, uint32_t& r1,
                                        uint32_t& r2, uint32_t& r3, uint32_t addr)
{
    asm volatile("ldmatrix.sync.aligned.m8n8.x4.shared.b16 {%0,%1,%2,%3}, [%4];"
                 : "=r"(r0), "=r"(r1), "=r"(r2), "=r"(r3) : "r"(addr));
}
__device__ __forceinline__ void ldsm_x4_t(uint32_t& r0, uint32_t& r1,
                                          uint32_t& r2, uint32_t& r3, uint32_t addr)
{
    asm volatile("ldmatrix.sync.aligned.m8n8.x4.trans.shared.b16 {%0,%1,%2,%3}, [%4];"
                 : "=r"(r0), "=r"(r1), "=r"(r2), "=r"(r3) : "r"(addr));
}
__device__ __forceinline__ void mma16816(float* d, const uint32_t* a, const uint32_t* b)
{
    asm volatile("mma.sync.aligned.m16n8k16.row.col.f32.bf16.bf16.f32 "
                 "{%0,%1,%2,%3}, {%4,%5,%6,%7}, {%8,%9}, {%0,%1,%2,%3};"
                 : "+f"(d[0]), "+f"(d[1]), "+f"(d[2]), "+f"(d[3])
                 : "r"(a[0]), "r"(a[1]), "r"(a[2]), "r"(a[3]), "r"(b[0]), "r"(b[1]));
}
__device__ __forceinline__ void cp_async16(uint32_t saddr, const void* gptr) {
    asm volatile("cp.async.cg.shared.global [%0], [%1], 16;" :: "r"(saddr), "l"(gptr));
}
#define CP_COMMIT() asm volatile("cp.async.commit_group;" ::: "memory")
#define CP_WAIT1()  asm volatile("cp.async.wait_group 1;" ::: "memory")
#define CP_WAIT2()  asm volatile("cp.async.wait_group 2;" ::: "memory")

// exp2 on the FMA pipe (no MUFU). Valid for y <= ~1; clamps below -100.
__device__ __forceinline__ float exp2_fast(float y) {
    y = fmaxf(y, -100.f);
    float z = y + 12582912.f;
    int   n = __float_as_int(z) - 0x4B400000;
    float f = y - (z - 12582912.f);
    float p =             1.3333558e-3f;
    p = fmaf(p, f, 9.6181291e-3f);
    p = fmaf(p, f, 5.5504109e-2f);
    p = fmaf(p, f, 2.4022651e-1f);
    p = fmaf(p, f, 6.9314718e-1f);
    p = fmaf(p, f, 1.0f);
    return p * __int_as_float((n + 127) << 23);
}
__device__ __forceinline__ uint32_t pack_bf16(float x, float y) {
    __nv_bfloat162 t = __floats2bfloat162_rn(x, y);
    return *(uint32_t*)&t;
}
__device__ __forceinline__ uint32_t pack_bf16_res(float x, float y, uint32_t hi) {
    __nv_bfloat162 h = *(__nv_bfloat162*)&hi;
    return pack_bf16(x - __bfloat162float(h.x), y - __bfloat162float(h.y));
}

// ---------------------------------------------------------------------------
// Elementwise helpers
// ---------------------------------------------------------------------------
__global__ void concat_w(const float* __restrict__ Wk, const float* __restrict__ Wv)
{
    int i = blockIdx.x * blockDim.x + threadIdx.x;
    int j = i >> 10, c = i & 1023;
    g_kvw[i] = (j < 64) ? Wk[j * EMB + c] : Wv[(j - 64) * EMB + c];
}

__global__ void split_hilo(const float* __restrict__ src,
                           __nv_bfloat16* __restrict__ hi,
                           __nv_bfloat16* __restrict__ lo, int n4)
{
    int i = blockIdx.x * blockDim.x + threadIdx.x;
    if (i >= n4) return;
    float4 v = ((const float4*)src)[i];
    __nv_bfloat16 h0 = __float2bfloat16(v.x), h1 = __float2bfloat16(v.y);
    __nv_bfloat16 h2 = __float2bfloat16(v.z), h3 = __float2bfloat16(v.w);
    __nv_bfloat16 l0 = __float2bfloat16(v.x - __bfloat162float(h0));
    __nv_bfloat16 l1 = __float2bfloat16(v.y - __bfloat162float(h1));
    __nv_bfloat16 l2 = __float2bfloat16(v.z - __bfloat162float(h2));
    __nv_bfloat16 l3 = __float2bfloat16(v.w - __bfloat162float(h3));
    ((__nv_bfloat162*)hi)[2 * i]     = __nv_bfloat162(h0, h1);
    ((__nv_bfloat162*)hi)[2 * i + 1] = __nv_bfloat162(h2, h3);
    ((__nv_bfloat162*)lo)[2 * i]     = __nv_bfloat162(l0, l1);
    ((__nv_bfloat162*)lo)[2 * i + 1] = __nv_bfloat162(l2, l3);
}

// ---------------------------------------------------------------------------
// bf16 3-split GEMM on mma.sync with 4-stage cp.async pipeline (round-4, passing)
// ---------------------------------------------------------------------------
#define NITER  96
#define STAGEB 20480
#define GSMEM  (4 * STAGEB)

__global__ __launch_bounds__(256, 1)
void gemm3_mma(const __nv_bfloat16* __restrict__ A0, const __nv_bfloat16* __restrict__ A1,
               const __nv_bfloat16* __restrict__ A2,
               const __nv_bfloat16* __restrict__ B0, const __nv_bfloat16* __restrict__ B1,
               const __nv_bfloat16* __restrict__ B2,
               const float* __restrict__ bias, float* __restrict__ C, int ldc)
{
    extern __shared__ __align__(16) char sm[];

    const int tid  = threadIdx.x;
    const int wid  = tid >> 5;
    const int lane = tid & 31;
    const int m0 = blockIdx.y * 128;
    const int n0 = blockIdx.x * 128;
    const int wm = (wid & 1) << 6;
    const int wn = (wid >> 1) << 5;

    const int lt = lane >> 3;
    const int lr = lane & 7;
    const uint32_t a_off = (uint32_t)(wm + lr + ((lt & 1) << 3)) * 80 + ((lt >> 1) << 4);
    const uint32_t b_off = 10240u + (uint32_t)(wn + lr + ((lt >> 1) << 3)) * 80 + ((lt & 1) << 4);
    const uint32_t sbase = smem_u32(sm);

    const int r0c = tid >> 2,         s0c = tid & 3;
    const int r1c = (tid + 256) >> 2, s1c = (tid + 256) & 3;

    float d[4][4][4];
#pragma unroll
    for (int mi = 0; mi < 4; mi++)
#pragma unroll
        for (int ni = 0; ni < 4; ni++)
#pragma unroll
            for (int q = 0; q < 4; q++) d[mi][ni][q] = 0.f;

#define LOAD_STAGE(bufi, ci) do {                                                  \
    const int _ph = (ci) >> 5;                                                     \
    const int _k0 = ((ci) & 31) << 5;                                              \
    const __nv_bfloat16* _Ap = (_ph == 0) ? A0 : (_ph == 1) ? A1 : A2;             \
    const __nv_bfloat16* _Bp = (_ph == 0) ? B0 : (_ph == 1) ? B1 : B2;             \
    const uint32_t _sb = sbase + (uint32_t)(bufi) * STAGEB;                        \
    cp_async16(_sb + (uint32_t)r0c * 80 + s0c * 16,                                \
               _Ap + (size_t)(m0 + r0c) * EMB + _k0 + s0c * 8);                    \
    cp_async16(_sb + (uint32_t)r1c * 80 + s1c * 16,                                \
               _Ap + (size_t)(m0 + r1c) * EMB + _k0 + s1c * 8);                    \
    cp_async16(_sb + 10240u + (uint32_t)r0c * 80 + s0c * 16,                       \
               _Bp + (size_t)(n0 + r0c) * EMB + _k0 + s0c * 8);                    \
    cp_async16(_sb + 10240u + (uint32_t)r1c * 80 + s1c * 16,                       \
               _Bp + (size_t)(n0 + r1c) * EMB + _k0 + s1c * 8);                    \
} while (0)

    LOAD_STAGE(0, 0); CP_COMMIT();
    LOAD_STAGE(1, 1); CP_COMMIT();
    LOAD_STAGE(2, 2); CP_COMMIT();

    for (int c = 0; c < NITER; c++) {
        CP_WAIT2();
        __syncthreads();

        if (c + 3 < NITER) LOAD_STAGE((c + 3) & 3, c + 3);
        CP_COMMIT();

        const uint32_t abase = sbase + (uint32_t)(c & 3) * STAGEB + a_off;
        const uint32_t bbase = sbase + (uint32_t)(c & 3) * STAGEB + b_off;
#pragma unroll
        for (int ks = 0; ks < 2; ks++) {
            uint32_t a[4][4], b[2][4];
#pragma unroll
            for (int mi = 0; mi < 4; mi++)
                ldsm_x4(a[mi][0], a[mi][1], a[mi][2], a[mi][3],
                        abase + (uint32_t)mi * (16 * 80) + ks * 32);
#pragma unroll
            for (int nt = 0; nt < 2; nt++)
                ldsm_x4(b[nt][0], b[nt][1], b[nt][2], b[nt][3],
                        bbase + (uint32_t)nt * (16 * 80) + ks * 32);
#pragma unroll
            for (int mi = 0; mi < 4; mi++)
#pragma unroll
                for (int ni = 0; ni < 4; ni++)
                    mma16816(d[mi][ni], a[mi], &b[ni >> 1][(ni & 1) * 2]);
        }
        __syncthreads();
    }

    const int erow = lane >> 2;
    const int ecol = (lane & 3) << 1;
#pragma unroll
    for (int mi = 0; mi < 4; mi++) {
#pragma unroll
        for (int ni = 0; ni < 4; ni++) {
            const int r = m0 + wm + mi * 16 + erow;
            const int cc = n0 + wn + ni * 8 + ecol;
            float bx = 0.f, by = 0.f;
            if (bias) { bx = bias[cc]; by = bias[cc + 1]; }
            float2* p0 = (float2*)(C + (size_t)r * ldc + cc);
            float2* p1 = (float2*)(C + (size_t)(r + 8) * ldc + cc);
            *p0 = make_float2(d[mi][ni][0] + bx, d[mi][ni][1] + by);
            *p1 = make_float2(d[mi][ni][2] + bx, d[mi][ni][3] + by);
        }
    }
#undef LOAD_STAGE
}

// ---------------------------------------------------------------------------
// Tensor-core causal MQA flash attention.
//   Block: 128 threads (4 warps), Q tile [128,64] (hi/lo bf16 smem),
//   KV tiles of 64 rows (hi/lo, 2-stage cp.async).
//   S = Qhi@Khi + Qlo@Khi + Qhi@Klo (3-term split).
//   PV = Phi@Vhi + Plo@Vhi + Phi@Vlo (3-term split).
//   Softmax on accumulator fragments; exp2 on FMA pipe.
// smem layout (row stride 144B -> conflict-free ldmatrix):
//   qhi @0 (18432), qlo @18432 | stages @36864: per stage (36864):
//   khi @0, klo @9216, vhi @18432, vlo @27648
// ---------------------------------------------------------------------------
#define QSTR   144
#define SM_QLO 18432
#define SM_KV  36864
#define STG    36864
#define ATT_SMEM (SM_KV + 2 * STG)   // 110592

__global__ __launch_bounds__(128, 1)
void mqa_attn_mma(const __nv_bfloat16* __restrict__ qhi,
                  const __nv_bfloat16* __restrict__ qlo,
                  const __nv_bfloat16* __restrict__ kvhi,
                  const __nv_bfloat16* __restrict__ kvlo,
                  float* __restrict__ y)
{
    extern __shared__ __align__(16) char sm[];
    const int qt   = (int)gridDim.x - 1 - (int)blockIdx.x;
    const int h    = blockIdx.y;
    const int b    = blockIdx.z;
    const int tid  = threadIdx.x;
    const int w    = tid >> 5;
    const int lane = tid & 31;
    const uint32_t sbase = smem_u32(sm);

    const int lt = lane >> 3;
    const int lr = lane & 7;
    // A-fragment (Q / also shape for K B-frag) lane offsets, stride 144
    const uint32_t a_loff = (uint32_t)(lr + ((lt & 1) << 3)) * QSTR + ((lt >> 1) << 4);
    const uint32_t b_loff = (uint32_t)(lr + ((lt >> 1) << 3)) * QSTR + ((lt & 1) << 4);
    const uint32_t v_loff = (uint32_t)(lr + ((lt & 1) << 3)) * QSTR + ((lt >> 1) << 4);

    // ---- load Q tile (contiguous 8 q_raw rows = [128,64]) into smem hi/lo ----
    {
        size_t qoff = ((size_t)b * SEQ + (size_t)(h * 128 + qt * 8)) * EMB;
        const uint4* sh = (const uint4*)(qhi + qoff);
        const uint4* sl = (const uint4*)(qlo + qoff);
#pragma unroll
        for (int i = 0; i < 8; i++) {
            int c = tid + i * 128;          // 0..1023 chunks of 16B
            int r = c >> 3, sg = c & 7;
            *(uint4*)(sm + r * QSTR + sg * 16)          = sh[c];
            *(uint4*)(sm + SM_QLO + r * QSTR + sg * 16) = sl[c];
        }
    }

#define LOAD_KV(bufi, s) do {                                                      \
    size_t _rb = ((size_t)b * SEQ + (size_t)(s) * 64) * 128;                       \
    const char* _sh = (const char*)(kvhi + _rb);                                   \
    const char* _sl = (const char*)(kvlo + _rb);                                   \
    uint32_t _sb = sbase + SM_KV + (uint32_t)(bufi) * STG;                         \
    _Pragma("unroll")                                                              \
    for (int _i = 0; _i < 8; _i++) {                                               \
        int _c = tid + _i * 128;                                                   \
        int _r = _c >> 4, _sg = _c & 15;                                           \
        uint32_t _d = (_sg < 8) ? (_sb + _r * QSTR + _sg * 16)                     \
                                : (_sb + 18432 + _r * QSTR + (_sg - 8) * 16);      \
        cp_async16(_d,        _sh + _r * 256 + _sg * 16);                          \
        cp_async16(_d + 9216, _sl + _r * 256 + _sg * 16);                          \
    }                                                                              \
} while (0)

    float O[2][8][4];
#pragma unroll
    for (int mi = 0; mi < 2; mi++)
#pragma unroll
        for (int nt = 0; nt < 8; nt++)
#pragma unroll
            for (int q = 0; q < 4; q++) O[mi][nt][q] = 0.f;
    float mrow[2][2] = {{-1e30f, -1e30f}, {-1e30f, -1e30f}};
    float lrow[2][2] = {{0.f, 0.f}, {0.f, 0.f}};

    const float QSC = 0.125f * 1.44269504088896340736f;
    const int ntl = 2 * qt + 2;

    LOAD_KV(0, 0); CP_COMMIT();

    for (int s = 0; s < ntl; s++) {
        __syncthreads();                       // everyone done reading buf (s+1)&1
        if (s + 1 < ntl) LOAD_KV((s + 1) & 1, s + 1);
        CP_COMMIT();
        CP_WAIT1();                            // stage s complete
        __syncthreads();

        const uint32_t kb = sbase + SM_KV + (uint32_t)(s & 1) * STG;

        // ---- S = Q @ K^T (3-term split) ----
        float S[2][8][4];
#pragma unroll
        for (int mi = 0; mi < 2; mi++)
#pragma unroll
            for (int nt = 0; nt < 8; nt++)
#pragma unroll
                for (int q = 0; q < 4; q++) S[mi][nt][q] = 0.f;

#pragma unroll
        for (int term = 0; term < 3; term++) {
            const uint32_t qb = sbase + (term == 1 ? SM_QLO : 0) + a_loff
                                + (uint32_t)(32 * w) * QSTR;
            const uint32_t kk = kb + (term == 2 ? 9216u : 0u) + b_loff;
#pragma unroll
            for (int ks = 0; ks < 4; ks++) {
                uint32_t a[2][4], bf[4][4];
#pragma unroll
                for (int mi = 0; mi < 2; mi++)
                    ldsm_x4(a[mi][0], a[mi][1], a[mi][2], a[mi][3],
                            qb + (uint32_t)mi * (16 * QSTR) + ks * 32);
#pragma unroll
                for (int n2 = 0; n2 < 4; n2++)
                    ldsm_x4(bf[n2][0], bf[n2][1], bf[n2][2], bf[n2][3],
                            kk + (uint32_t)n2 * (16 * QSTR) + ks * 32);
#pragma unroll
                for (int mi = 0; mi < 2; mi++)
#pragma unroll
                    for (int nt = 0; nt < 8; nt++)
                        mma16816(S[mi][nt], a[mi], &bf[nt >> 1][(nt & 1) * 2]);
            }
        }

        // ---- mask (diagonal tiles only) + scale ----
        if (s >= 2 * qt) {
#pragma unroll
            for (int mi = 0; mi < 2; mi++) {
                const int r0 = qt * 128 + 32 * w + 16 * mi + (lane >> 2);
#pragma unroll
                for (int nt = 0; nt < 8; nt++) {
                    const int jb = s * 64 + nt * 8 + 2 * (lane & 3);
                    if (jb     > r0)     S[mi][nt][0] = -1e30f;
                    if (jb + 1 > r0)     S[mi][nt][1] = -1e30f;
                    if (jb     > r0 + 8) S[mi][nt][2] = -1e30f;
                    if (jb + 1 > r0 + 8) S[mi][nt][3] = -1e30f;
                }
            }
        }
#pragma unroll
        for (int mi = 0; mi < 2; mi++)
#pragma unroll
            for (int nt = 0; nt < 8; nt++)
#pragma unroll
                for (int q = 0; q < 4; q++) S[mi][nt][q] *= QSC;

        // ---- online softmax on fragments ----
        uint32_t phi[2][4][4], plo[2][4][4];
#pragma unroll
        for (int mi = 0; mi < 2; mi++) {
            float t0 = -1e30f, t1 = -1e30f;
#pragma unroll
            for (int nt = 0; nt < 8; nt++) {
                t0 = fmaxf(t0, fmaxf(S[mi][nt][0], S[mi][nt][1]));
                t1 = fmaxf(t1, fmaxf(S[mi][nt][2], S[mi][nt][3]));
            }
            t0 = fmaxf(t0, __shfl_xor_sync(0xffffffffu, t0, 1));
            t0 = fmaxf(t0, __shfl_xor_sync(0xffffffffu, t0, 2));
            t1 = fmaxf(t1, __shfl_xor_sync(0xffffffffu, t1, 1));
            t1 = fmaxf(t1, __shfl_xor_sync(0xffffffffu, t1, 2));
            const float m0n = fmaxf(mrow[mi][0], t0);
            const float m1n = fmaxf(mrow[mi][1], t1);
            const float c0 = exp2_fast(mrow[mi][0] - m0n);
            const float c1 = exp2_fast(mrow[mi][1] - m1n);
            mrow[mi][0] = m0n; mrow[mi][1] = m1n;
            lrow[mi][0] *= c0; lrow[mi][1] *= c1;
#pragma unroll
            for (int nt = 0; nt < 8; nt++) {
                O[mi][nt][0] *= c0; O[mi][nt][1] *= c0;
                O[mi][nt][2] *= c1; O[mi][nt][3] *= c1;
            }
            float ps0 = 0.f, ps1 = 0.f;
#pragma unroll
            for (int nt = 0; nt < 8; nt++) {
                float p0 = exp2_fast(S[mi][nt][0] - m0n);
                float p1 = exp2_fast(S[mi][nt][1] - m0n);
                float p2 = exp2_fast(S[mi][nt][2] - m1n);
                float p3 = exp2_fast(S[mi][nt][3] - m1n);
                ps0 += p0 + p1; ps1 += p2 + p3;
                S[mi][nt][0] = p0; S[mi][nt][1] = p1;
                S[mi][nt][2] = p2; S[mi][nt][3] = p3;
            }
            lrow[mi][0] += ps0; lrow[mi][1] += ps1;
            // pack P -> bf16 hi/lo A-fragments (C layout == A layout)
#pragma unroll
            for (int ks = 0; ks < 4; ks++) {
                phi[mi][ks][0] = pack_bf16(S[mi][2*ks][0],   S[mi][2*ks][1]);
                phi[mi][ks][1] = pack_bf16(S[mi][2*ks][2],   S[mi][2*ks][3]);
                phi[mi][ks][2] = pack_bf16(S[mi][2*ks+1][0], S[mi][2*ks+1][1]);
                phi[mi][ks][3] = pack_bf16(S[mi][2*ks+1][2], S[mi][2*ks+1][3]);
                plo[mi][ks][0] = pack_bf16_res(S[mi][2*ks][0],   S[mi][2*ks][1],   phi[mi][ks][0]);
                plo[mi][ks][1] = pack_bf16_res(S[mi][2*ks][2],   S[mi][2*ks][3],   phi[mi][ks][1]);
                plo[mi][ks][2] = pack_bf16_res(S[mi][2*ks+1][0], S[mi][2*ks+1][1], phi[mi][ks][2]);
                plo[mi][ks][3] = pack_bf16_res(S[mi][2*ks+1][2], S[mi][2*ks+1][3], phi[mi][ks][3]);
            }
        }

        // ---- O += P @ V (3-term split) ----
#pragma unroll
        for (int ks = 0; ks < 4; ks++) {
            uint32_t vh[4][4];
#pragma unroll
            for (int ng = 0; ng < 4; ng++)
                ldsm_x4_t(vh[ng][0], vh[ng][1], vh[ng][2], vh[ng][3],
                          kb + 18432u + v_loff + (uint32_t)ks * (16 * QSTR) + ng * 32);
#pragma unroll
            for (int mi = 0; mi < 2; mi++)
#pragma unroll
                for (int nt = 0; nt < 8; nt++) {
                    const uint32_t* bb = &vh[nt >> 1][(nt & 1) * 2];
                    mma16816(O[mi][nt], phi[mi][ks], bb);
                    mma16816(O[mi][nt], plo[mi][ks], bb);
                }
        }
#pragma unroll
        for (int ks = 0; ks < 4; ks++) {
            uint32_t vl[4][4];
#pragma unroll
            for (int ng = 0; ng < 4; ng++)
                ldsm_x4_t(vl[ng][0], vl[ng][1], vl[ng][2], vl[ng][3],
                          kb + 27648u + v_loff + (uint32_t)ks * (16 * QSTR) + ng * 32);
#pragma unroll
            for (int mi = 0; mi < 2; mi++)
#pragma unroll
                for (int nt = 0; nt < 8; nt++)
                    mma16816(O[mi][nt], phi[mi][ks], &vl[nt >> 1][(nt & 1) * 2]);
        }
    }

    // ---- finalize: quad-reduce l, normalize, store ----
#pragma unroll
    for (int mi = 0; mi < 2; mi++) {
        float l0 = lrow[mi][0], l1 = lrow[mi][1];
        l0 += __shfl_xor_sync(0xffffffffu, l0, 1);
        l0 += __shfl_xor_sync(0xffffffffu, l0, 2);
        l1 += __shfl_xor_sync(0xffffffffu, l1, 1);
        l1 += __shfl_xor_sync(0xffffffffu, l1, 2);
        const float i0 = 1.f / l0, i1 = 1.f / l1;
        const int r0 = qt * 128 + 32 * w + 16 * mi + (lane >> 2);
#pragma unroll
        for (int nt = 0; nt < 8; nt++) {
            const int col = h * HS + nt * 8 + 2 * (lane & 3);
            *(float2*)(y + ((size_t)b * SEQ + r0) * EMB + col) =
                make_float2(O[mi][nt][0] * i0, O[mi][nt][1] * i0);
            *(float2*)(y + ((size_t)b * SEQ + r0 + 8) * EMB + col) =
                make_float2(O[mi][nt][2] * i1, O[mi][nt][3] * i1);
        }
    }
#undef LOAD_KV
}

// ---------------------------------------------------------------------------
extern "C" void kernel_launch(void* const* d_in, const int* in_sizes, int n_in,
                              void* d_out, int out_size)
{
    const float* x  = (const float*)d_in[0];
    const float* Wk = (const float*)d_in[1];
    const float* Wv = (const float*)d_in[2];
    const float* Wq = (const float*)d_in[3];
    const float* Wp = (const float*)d_in[4];
    const float* bp = (const float*)d_in[5];
    float* out = (float*)d_out;

    float *qb, *kvb, *yb, *kvw;
    cudaGetSymbolAddress((void**)&qb,  g_q);
    cudaGetSymbolAddress((void**)&kvb, g_kv);
    cudaGetSymbolAddress((void**)&yb,  g_y);
    cudaGetSymbolAddress((void**)&kvw, g_kvw);
    __nv_bfloat16 *xhi, *xlo, *yhi, *ylo, *wqhi, *wqlo, *wphi, *wplo, *kvwhi, *kvwlo, *kvhi, *kvlo;
    cudaGetSymbolAddress((void**)&xhi, g_xhi);   cudaGetSymbolAddress((void**)&xlo, g_xlo);
    cudaGetSymbolAddress((void**)&yhi, g_yhi);   cudaGetSymbolAddress((void**)&ylo, g_ylo);
    cudaGetSymbolAddress((void**)&wqhi, g_wqhi); cudaGetSymbolAddress((void**)&wqlo, g_wqlo);
    cudaGetSymbolAddress((void**)&wphi, g_wphi); cudaGetSymbolAddress((void**)&wplo, g_wplo);
    cudaGetSymbolAddress((void**)&kvwhi, g_kvwhi); cudaGetSymbolAddress((void**)&kvwlo, g_kvwlo);
    cudaGetSymbolAddress((void**)&kvhi, g_kvhi); cudaGetSymbolAddress((void**)&kvlo, g_kvlo);

    cudaFuncSetAttribute(gemm3_mma, cudaFuncAttributeMaxDynamicSharedMemorySize, GSMEM);
    cudaFuncSetAttribute(mqa_attn_mma, cudaFuncAttributeMaxDynamicSharedMemorySize, ATT_SMEM);

    // precision splits
    concat_w<<<512, 256>>>(Wk, Wv);
    split_hilo<<<(MROWS * EMB / 4 + 255) / 256, 256>>>(x,   xhi,  xlo,  MROWS * EMB / 4);
    split_hilo<<<(128 * EMB / 4 + 255) / 256, 256>>>(kvw, kvwhi, kvwlo, 128 * EMB / 4);
    split_hilo<<<(EMB * EMB / 4 + 255) / 256, 256>>>(Wq,  wqhi, wqlo, EMB * EMB / 4);
    split_hilo<<<(EMB * EMB / 4 + 255) / 256, 256>>>(Wp,  wphi, wplo, EMB * EMB / 4);

    // kv = x @ [Wk;Wv]^T  -> [4096,128]
    gemm3_mma<<<dim3(1, MROWS / 128), 256, GSMEM>>>(
        xhi, xhi, xlo, kvwhi, kvwlo, kvwhi, nullptr, kvb, 128);

    // q = x @ Wq^T        -> [4096,1024]
    gemm3_mma<<<dim3(EMB / 128, MROWS / 128), 256, GSMEM>>>(
        xhi, xhi, xlo, wqhi, wqlo, wqhi, nullptr, qb, EMB);

    // split kv and q to bf16 hi/lo (x splits no longer needed -> reuse for q)
    split_hilo<<<(MROWS * 128 / 4 + 255) / 256, 256>>>(kvb, kvhi, kvlo, MROWS * 128 / 4);
    split_hilo<<<(MROWS * EMB / 4 + 255) / 256, 256>>>(qb, xhi, xlo, MROWS * EMB / 4);

    // tensor-core flash attention
    mqa_attn_mma<<<dim3(SEQ / 128, NHEAD, BATCH), 128, ATT_SMEM>>>(
        xhi, xlo, kvhi, kvlo, yb);

    // out = y @ Wp^T + bp
    split_hilo<<<(MROWS * EMB / 4 + 255) / 256, 256>>>(yb, yhi, ylo, MROWS * EMB / 4);
    gemm3_mma<<<dim3(EMB / 128, MROWS / 128), 256, GSMEM>>>(
        yhi, yhi, ylo, wphi, wplo, wphi, bp, out, EMB);
}